// round 2
// baseline (speedup 1.0000x reference)
#include <cuda_runtime.h>
#include <math.h>

// ---------------- problem constants ----------------
#define BI    4
#define NN    1024
#define DIN   2048
#define SD    512
#define NH    8
#define NF    8
#define NC    20
#define NODES (BI*NN)            // 4096
#define WALLN 876                // 512 sim | 64 gat1 | 60 ref | 240 bbox
#define COL_H1   512
#define COL_REF  576
#define COL_BBOX 636

// output layout (flattened tuple, f32)
#define OUT_NODE  80
#define OUT_REF   82000
#define OUT_BBOX  327760
#define OUT_TOTAL 1310800

// ---------------- scratch (static device memory; no allocs) ----------------
__device__ float g_Wall[DIN*WALLN];      // packed weights [K=2048][876]
__device__ float g_Call[NODES*WALLN];    // packed GEMM out [4096][876]
__device__ float g_SF[NODES*SD];         // normalized sim features
__device__ float g_ES1[NODES*NH];
__device__ float g_ED1[NODES*NH];
__device__ unsigned g_M1[BI*NH];         // encoded per-(img,head) max of es1
__device__ float g_N1[NODES*64];         // elu(gat1 out)
__device__ float g_H2[NODES*NC];
__device__ float g_ES2[NODES];
__device__ float g_ED2[NODES];
__device__ unsigned g_M2[BI];
__device__ float g_N2[NODES*NC];
__device__ unsigned char g_iouM[(size_t)BI*NN*NN];
__device__ unsigned char g_simM[(size_t)BI*NN*NN];

// monotonic float<->uint encoding for atomicMax
__device__ __forceinline__ unsigned fenc(float f) {
    unsigned u = __float_as_uint(f);
    return (u & 0x80000000u) ? ~u : (u | 0x80000000u);
}
__device__ __forceinline__ float fdec(unsigned u) {
    u = (u & 0x80000000u) ? (u & 0x7fffffffu) : ~u;
    return __uint_as_float(u);
}
__device__ __forceinline__ float lrelu(float x) { return x > 0.f ? x : 0.2f * x; }

// ---------------- kernels ----------------
__global__ void init_kernel() {
    int t = threadIdx.x;
    if (t < BI*NH) g_M1[t] = 0u;
    if (t < BI)    g_M2[t] = 0u;
}

__global__ void pack_kernel(const float* __restrict__ simW, const float* __restrict__ gat1W,
                            const float* __restrict__ refW, const float* __restrict__ bboxW) {
    int idx = blockIdx.x * blockDim.x + threadIdx.x;
    if (idx >= DIN*WALLN) return;
    int k = idx / WALLN, j = idx % WALLN;
    float v;
    if (j < COL_H1)        v = simW[k*SD + j];
    else if (j < COL_REF)  v = gat1W[k*64 + (j - COL_H1)];
    else if (j < COL_BBOX) { int jj = j - COL_REF;  int t = jj/NC; int c = jj%NC;
                             v = refW[(size_t)t*DIN*NC + (size_t)k*NC + c]; }
    else                   { int jj = j - COL_BBOX; int t = jj/80; int c = jj%80;
                             v = bboxW[(size_t)t*DIN*80 + (size_t)k*80 + c]; }
    g_Wall[idx] = v;
}

// C[4096,876] = A[4096,2048] @ g_Wall[2048,876]; BM=128 BN=64 BK=8, 8x4 microtile
__global__ __launch_bounds__(256) void sgemm_big(const float* __restrict__ A) {
    __shared__ float As[8][128];
    __shared__ float Bs[8][64];
    const int tid = threadIdx.x;
    const int m0 = blockIdx.y * 128, n0 = blockIdx.x * 64;
    const int arow = tid >> 1, acol = (tid & 1) * 4;
    const int brow = tid >> 5, bcol = (tid & 31) * 2;
    const int tx = tid & 15, ty = tid >> 4;
    const int rm = ty * 8, rn = tx * 4;
    float acc[8][4];
#pragma unroll
    for (int i = 0; i < 8; i++)
#pragma unroll
        for (int j = 0; j < 4; j++) acc[i][j] = 0.f;

    for (int k0 = 0; k0 < DIN; k0 += 8) {
        float4 av = *(const float4*)(A + (size_t)(m0 + arow) * DIN + k0 + acol);
        float2 bv;
        int bn = n0 + bcol;
        if (bn + 1 < WALLN) bv = *(const float2*)(g_Wall + (size_t)(k0 + brow) * WALLN + bn);
        else { bv.x = (bn < WALLN) ? g_Wall[(size_t)(k0 + brow) * WALLN + bn] : 0.f; bv.y = 0.f; }
        __syncthreads();
        As[acol+0][arow] = av.x; As[acol+1][arow] = av.y;
        As[acol+2][arow] = av.z; As[acol+3][arow] = av.w;
        Bs[brow][bcol] = bv.x; Bs[brow][bcol+1] = bv.y;
        __syncthreads();
#pragma unroll
        for (int kk = 0; kk < 8; kk++) {
            float a[8], b[4];
#pragma unroll
            for (int i = 0; i < 8; i++) a[i] = As[kk][rm + i];
#pragma unroll
            for (int j = 0; j < 4; j++) b[j] = Bs[kk][rn + j];
#pragma unroll
            for (int i = 0; i < 8; i++)
#pragma unroll
                for (int j = 0; j < 4; j++) acc[i][j] = fmaf(a[i], b[j], acc[i][j]);
        }
    }
#pragma unroll
    for (int i = 0; i < 8; i++)
#pragma unroll
        for (int j = 0; j < 4; j++) {
            int cn = n0 + rn + j;
            if (cn < WALLN) g_Call[(size_t)(m0 + rm + i) * WALLN + cn] = acc[i][j];
        }
}

// per-row L2 normalize of sim features (adds sim_b)
__global__ void normalize_kernel(const float* __restrict__ simb) {
    int r = blockIdx.x, tid = threadIdx.x;  // 128 threads
    const float* row = g_Call + (size_t)r * WALLN;
    float ss = 0.f;
    for (int c = tid; c < SD; c += 128) { float v = row[c] + simb[c]; ss += v * v; }
#pragma unroll
    for (int off = 16; off > 0; off >>= 1) ss += __shfl_xor_sync(0xffffffffu, ss, off);
    __shared__ float red[4];
    if ((tid & 31) == 0) red[tid >> 5] = ss;
    __syncthreads();
    float tot = red[0] + red[1] + red[2] + red[3];
    float inv = 1.f / (sqrtf(tot) + 1e-9f);
    for (int c = tid; c < SD; c += 128) {
        float v = row[c] + simb[c];
        g_SF[(size_t)r * SD + c] = v * inv;
    }
}

__global__ void edge1_kernel(const float* __restrict__ asrc, const float* __restrict__ adst) {
    int n = blockIdx.x * blockDim.x + threadIdx.x;
    if (n >= NODES) return;
    const float* h = g_Call + (size_t)n * WALLN + COL_H1;
    int img = n >> 10;
#pragma unroll
    for (int hh = 0; hh < NH; hh++) {
        float es = 0.f, ed = 0.f;
#pragma unroll
        for (int f = 0; f < NF; f++) {
            float v = h[hh * NF + f];
            es = fmaf(v, asrc[hh * NF + f], es);
            ed = fmaf(v, adst[hh * NF + f], ed);
        }
        g_ES1[n * NH + hh] = es;
        g_ED1[n * NH + hh] = ed;
        atomicMax(&g_M1[img * NH + hh], fenc(es));
    }
}

// IoU edge mask (byte per pair), 16 dsts per block
__global__ void iou_kernel(const float* __restrict__ boxes) {
    __shared__ float4 bx[NN];
    int img = blockIdx.y, tid = threadIdx.x;
    const float4* bsrc = (const float4*)(boxes + (size_t)img * NN * 4);
    for (int i = tid; i < NN; i += 256) bx[i] = bsrc[i];
    __syncthreads();
    unsigned char* M = g_iouM + (size_t)img * NN * NN;
    for (int idx = tid; idx < 16 * NN; idx += 256) {
        int dl = idx >> 10, s = idx & 1023;
        int d = blockIdx.x * 16 + dl;
        float4 A = bx[d], Bb = bx[s];
        float areaA = (A.z - A.x) * (A.w - A.y);
        float areaB = (Bb.z - Bb.x) * (Bb.w - Bb.y);
        float lx = fmaxf(A.x, Bb.x), ly = fmaxf(A.y, Bb.y);
        float rx = fminf(A.z, Bb.z), ry = fminf(A.w, Bb.w);
        float w = fmaxf(rx - lx, 0.f), hh = fmaxf(ry - ly, 0.f);
        float inter = w * hh;
        float iou = inter / (areaA + areaB - inter + 1e-9f);
        M[(size_t)d * NN + s] = (unsigned char)((iou >= 0.4f) || (s == d));
    }
}

// GAT1 aggregation: warp per dst, 8 dsts per block, smem-staged src chunks
__global__ __launch_bounds__(256) void gat1_agg_kernel(const float* __restrict__ b1) {
    int img = blockIdx.y;
    int warp = threadIdx.x >> 5, lane = threadIdx.x & 31;
    int d = blockIdx.x * 8 + warp;
    int gd = img * NN + d;
    __shared__ float sh_h1[128][65];
    __shared__ float sh_es[128][9];
    __shared__ unsigned char sh_m[8][128];
    float acc[64], den[NH], ed[NH], shift[NH];
#pragma unroll
    for (int i = 0; i < 64; i++) acc[i] = 0.f;
#pragma unroll
    for (int h = 0; h < NH; h++) {
        den[h] = 0.f;
        ed[h] = g_ED1[gd * NH + h];
        shift[h] = lrelu(fdec(g_M1[img * NH + h]) + ed[h]);
    }
    for (int c0 = 0; c0 < NN; c0 += 128) {
        __syncthreads();
        for (int i = threadIdx.x; i < 128 * 64; i += 256) {
            int r = i >> 6, c = i & 63;
            sh_h1[r][c] = g_Call[(size_t)(img * NN + c0 + r) * WALLN + COL_H1 + c];
        }
        for (int i = threadIdx.x; i < 128 * 8; i += 256) {
            int r = i >> 3, c = i & 7;
            sh_es[r][c] = g_ES1[(img * NN + c0 + r) * NH + c];
        }
        {
            const unsigned* mrow = (const unsigned*)(g_iouM + (size_t)img * NN * NN + (size_t)d * NN + c0);
            ((unsigned*)sh_m[warp])[lane] = mrow[lane];
        }
        __syncthreads();
        for (int p = 0; p < 4; p++) {
            int sl = p * 32 + lane;
            bool mb = sh_m[warp][sl] != 0;
            if (!__any_sync(0xffffffffu, mb)) continue;
            if (mb) {
#pragma unroll
                for (int h = 0; h < NH; h++) {
                    float w = __expf(lrelu(sh_es[sl][h] + ed[h]) - shift[h]);
                    den[h] += w;
#pragma unroll
                    for (int f = 0; f < NF; f++)
                        acc[h * 8 + f] = fmaf(w, sh_h1[sl][h * 8 + f], acc[h * 8 + f]);
                }
            }
        }
    }
#pragma unroll
    for (int off = 16; off > 0; off >>= 1) {
#pragma unroll
        for (int i = 0; i < 64; i++) acc[i] += __shfl_xor_sync(0xffffffffu, acc[i], off);
#pragma unroll
        for (int h = 0; h < NH; h++) den[h] += __shfl_xor_sync(0xffffffffu, den[h], off);
    }
    if (lane == 0) {
#pragma unroll
        for (int i = 0; i < 64; i++) {
            float v = acc[i] / den[i >> 3] + b1[i];
            g_N1[(size_t)gd * 64 + i] = v > 0.f ? v : expm1f(v);
        }
    }
}

__global__ void gat2_prep_kernel(const float* __restrict__ W2,
                                 const float* __restrict__ asrc2,
                                 const float* __restrict__ adst2) {
    int n = blockIdx.x * blockDim.x + threadIdx.x;
    if (n >= NODES) return;
    int img = n >> 10;
    float x[64];
#pragma unroll
    for (int k = 0; k < 64; k++) x[k] = g_N1[(size_t)n * 64 + k];
    float es = 0.f, ed = 0.f;
    for (int c = 0; c < NC; c++) {
        float a = 0.f;
#pragma unroll
        for (int k = 0; k < 64; k++) a = fmaf(x[k], W2[k * NC + c], a);
        g_H2[n * NC + c] = a;
        es = fmaf(a, asrc2[c], es);
        ed = fmaf(a, adst2[c], ed);
    }
    g_ES2[n] = es;
    g_ED2[n] = ed;
    atomicMax(&g_M2[img], fenc(es));
}

// per-image gram of normalized sim features -> byte mask. BM=128(s) BN=64(d) BK=8
__global__ __launch_bounds__(256) void gram_kernel() {
    int img = blockIdx.z;
    const float* A = g_SF + (size_t)img * NN * SD;
    __shared__ float As[8][128];
    __shared__ float Bs[8][64];
    const int tid = threadIdx.x;
    const int m0 = blockIdx.y * 128, n0 = blockIdx.x * 64;
    const int arow = tid >> 1, acol = (tid & 1) * 4;
    const int brow = tid >> 2, bcol = (tid & 3) * 2;
    const int tx = tid & 15, ty = tid >> 4;
    const int rm = ty * 8, rn = tx * 4;
    float acc[8][4];
#pragma unroll
    for (int i = 0; i < 8; i++)
#pragma unroll
        for (int j = 0; j < 4; j++) acc[i][j] = 0.f;
    for (int k0 = 0; k0 < SD; k0 += 8) {
        float4 av = *(const float4*)(A + (size_t)(m0 + arow) * SD + k0 + acol);
        float2 bv = *(const float2*)(A + (size_t)(n0 + brow) * SD + k0 + bcol);
        __syncthreads();
        As[acol+0][arow] = av.x; As[acol+1][arow] = av.y;
        As[acol+2][arow] = av.z; As[acol+3][arow] = av.w;
        Bs[bcol][brow] = bv.x; Bs[bcol+1][brow] = bv.y;
        __syncthreads();
#pragma unroll
        for (int kk = 0; kk < 8; kk++) {
            float a[8], b[4];
#pragma unroll
            for (int i = 0; i < 8; i++) a[i] = As[kk][rm + i];
#pragma unroll
            for (int j = 0; j < 4; j++) b[j] = Bs[kk][rn + j];
#pragma unroll
            for (int i = 0; i < 8; i++)
#pragma unroll
                for (int j = 0; j < 4; j++) acc[i][j] = fmaf(a[i], b[j], acc[i][j]);
        }
    }
    unsigned char* M = g_simM + (size_t)img * NN * NN;
#pragma unroll
    for (int i = 0; i < 8; i++)
#pragma unroll
        for (int j = 0; j < 4; j++) {
            int s = m0 + rm + i, dd = n0 + rn + j;
            M[(size_t)dd * NN + s] = (unsigned char)((acc[i][j] >= 0.4f) || (s == dd));
        }
}

__global__ __launch_bounds__(256) void gat2_agg_kernel(const float* __restrict__ b2) {
    int img = blockIdx.y;
    int warp = threadIdx.x >> 5, lane = threadIdx.x & 31;
    int d = blockIdx.x * 8 + warp;
    int gd = img * NN + d;
    __shared__ float sh_h2[128][21];
    __shared__ float sh_es[128];
    __shared__ unsigned char sh_m[8][128];
    float acc[NC], den = 0.f;
#pragma unroll
    for (int c = 0; c < NC; c++) acc[c] = 0.f;
    float ed = g_ED2[gd];
    float shift = lrelu(fdec(g_M2[img]) + ed);
    for (int c0 = 0; c0 < NN; c0 += 128) {
        __syncthreads();
        for (int i = threadIdx.x; i < 128 * NC; i += 256) {
            int r = i / NC, c = i % NC;
            sh_h2[r][c] = g_H2[(img * NN + c0 + r) * NC + c];
        }
        if (threadIdx.x < 128) sh_es[threadIdx.x] = g_ES2[img * NN + c0 + threadIdx.x];
        {
            const unsigned* mrow = (const unsigned*)(g_simM + (size_t)img * NN * NN + (size_t)d * NN + c0);
            ((unsigned*)sh_m[warp])[lane] = mrow[lane];
        }
        __syncthreads();
        for (int p = 0; p < 4; p++) {
            int sl = p * 32 + lane;
            bool mb = sh_m[warp][sl] != 0;
            if (!__any_sync(0xffffffffu, mb)) continue;
            if (mb) {
                float w = __expf(lrelu(sh_es[sl] + ed) - shift);
                den += w;
#pragma unroll
                for (int c = 0; c < NC; c++) acc[c] = fmaf(w, sh_h2[sl][c], acc[c]);
            }
        }
    }
#pragma unroll
    for (int off = 16; off > 0; off >>= 1) {
#pragma unroll
        for (int c = 0; c < NC; c++) acc[c] += __shfl_xor_sync(0xffffffffu, acc[c], off);
        den += __shfl_xor_sync(0xffffffffu, den, off);
    }
    if (lane == 0) {
#pragma unroll
        for (int c = 0; c < NC; c++) g_N2[(size_t)gd * NC + c] = acc[c] / den + b2[c];
    }
}

__global__ void node_kernel(const float* __restrict__ nW, const float* __restrict__ nb,
                            float* __restrict__ out) {
    int n = blockIdx.x * blockDim.x + threadIdx.x;
    if (n >= NODES) return;
    float x[NC], v[NC];
#pragma unroll
    for (int c = 0; c < NC; c++) x[c] = g_N2[(size_t)n * NC + c];
#pragma unroll
    for (int c = 0; c < NC; c++) {
        float a = nb[c];
#pragma unroll
        for (int cc = 0; cc < NC; cc++) a = fmaf(x[cc], nW[cc * NC + c], a);
        v[c] = a;
    }
    float m = v[0];
#pragma unroll
    for (int c = 1; c < NC; c++) m = fmaxf(m, v[c]);
    float s = 0.f;
#pragma unroll
    for (int c = 0; c < NC; c++) { v[c] = __expf(v[c] - m); s += v[c]; }
    float inv = 1.f / s;
#pragma unroll
    for (int c = 0; c < NC; c++) out[OUT_NODE + (size_t)n * NC + c] = v[c] * inv;
}

__global__ void graph_kernel(float* __restrict__ out) {
    int img = blockIdx.x, c = blockIdx.y, tid = threadIdx.x;  // 256 threads
    float s = 0.f;
    for (int node = tid; node < NN; node += 256)
        s += out[OUT_NODE + (size_t)(img * NN + node) * NC + c];
#pragma unroll
    for (int off = 16; off > 0; off >>= 1) s += __shfl_xor_sync(0xffffffffu, s, off);
    __shared__ float red[8];
    if ((tid & 31) == 0) red[tid >> 5] = s;
    __syncthreads();
    if (tid == 0) {
        float tot = 0.f;
#pragma unroll
        for (int i = 0; i < 8; i++) tot += red[i];
        out[img * NC + c] = tot * (1.f / (float)NN);
    }
}

__global__ void scatter_kernel(const float* __restrict__ refb, const float* __restrict__ bboxb,
                               float* __restrict__ out) {
    int idx = blockIdx.x * blockDim.x + threadIdx.x;
    const int REF_TOT = 3 * NODES * NC;       // 245760
    const int BBOX_TOT = 3 * NODES * 80;      // 983040
    if (idx < REF_TOT) {
        int k = idx / (NODES * NC), r = idx % (NODES * NC);
        int n = r / NC, c = r % NC;
        out[OUT_REF + idx] = g_Call[(size_t)n * WALLN + COL_REF + k * NC + c] + refb[k * NC + c];
    } else {
        int j = idx - REF_TOT;
        if (j >= BBOX_TOT) return;
        int k = j / (NODES * 80), r = j % (NODES * 80);
        int n = r / 80, c = r % 80;
        out[OUT_BBOX + j] = g_Call[(size_t)n * WALLN + COL_BBOX + k * 80 + c] + bboxb[k * 80 + c];
    }
}

// ---------------- launch ----------------
extern "C" void kernel_launch(void* const* d_in, const int* in_sizes, int n_in,
                              void* d_out, int out_size) {
    const float* x1     = (const float*)d_in[0];
    const float* boxes  = (const float*)d_in[1];
    const float* simW   = (const float*)d_in[2];
    const float* simb   = (const float*)d_in[3];
    const float* gat1W  = (const float*)d_in[4];
    const float* asrc1  = (const float*)d_in[5];
    const float* adst1  = (const float*)d_in[6];
    const float* b1     = (const float*)d_in[7];
    const float* gat2W  = (const float*)d_in[8];
    const float* asrc2  = (const float*)d_in[9];
    const float* adst2  = (const float*)d_in[10];
    const float* b2     = (const float*)d_in[11];
    const float* nodeW  = (const float*)d_in[12];
    const float* nodeb  = (const float*)d_in[13];
    const float* refW   = (const float*)d_in[14];
    const float* refb   = (const float*)d_in[15];
    const float* bboxW  = (const float*)d_in[16];
    const float* bboxb  = (const float*)d_in[17];
    float* out = (float*)d_out;

    init_kernel<<<1, 64>>>();
    pack_kernel<<<(DIN * WALLN + 255) / 256, 256>>>(simW, gat1W, refW, bboxW);
    sgemm_big<<<dim3((WALLN + 63) / 64, NODES / 128), 256>>>(x1);
    normalize_kernel<<<NODES, 128>>>(simb);
    edge1_kernel<<<NODES / 256, 256>>>(asrc1, adst1);
    iou_kernel<<<dim3(NN / 16, BI), 256>>>(boxes);
    gat1_agg_kernel<<<dim3(NN / 8, BI), 256>>>(b1);
    gat2_prep_kernel<<<NODES / 256, 256>>>(gat2W, asrc2, adst2);
    gram_kernel<<<dim3(NN / 64, NN / 128, BI), 256>>>();
    gat2_agg_kernel<<<dim3(NN / 8, BI), 256>>>(b2);
    node_kernel<<<NODES / 256, 256>>>(nodeW, nodeb, out);
    graph_kernel<<<dim3(BI, NC), 256>>>(out);
    scatter_kernel<<<(3 * NODES * NC + 3 * NODES * 80 + 255) / 256, 256>>>(refb, bboxb, out);
}

// round 3
// speedup vs baseline: 1.3161x; 1.3161x over previous
#include <cuda_runtime.h>
#include <math.h>

// ---------------- problem constants ----------------
#define BI    4
#define NN    1024
#define DIN   2048
#define SD    512
#define NH    8
#define NF    8
#define NC    20
#define NODES (BI*NN)            // 4096
#define WALLN 876                // 512 sim | 64 gat1 | 60 ref | 240 bbox
#define WALLP 896                // padded to 14*64
#define COL_H1   512
#define COL_REF  576
#define COL_BBOX 636

// output layout (flattened tuple, f32)
#define OUT_NODE  80
#define OUT_REF   82000
#define OUT_BBOX  327760

// smem strides (both ≡ 8 mod 32 for conflict-free fragment gathers)
#define ASTR 136
#define BSTR 72

// ---------------- scratch (static device memory; no allocs) ----------------
__device__ float g_Wall[DIN*WALLP];      // packed weights [K=2048][896]
__device__ float g_Call[(size_t)NODES*WALLP];    // packed GEMM out [4096][896]
__device__ float g_SF[NODES*SD];         // normalized sim features
__device__ float g_ES1[NODES*NH];
__device__ float g_ED1[NODES*NH];
__device__ unsigned g_M1[BI*NH];         // encoded per-(img,head) max of es1
__device__ float g_N1[NODES*64];         // elu(gat1 out)
__device__ float g_H2[NODES*NC];
__device__ float g_ES2[NODES];
__device__ float g_ED2[NODES];
__device__ unsigned g_M2[BI];
__device__ float g_N2[NODES*NC];
__device__ unsigned char g_iouM[(size_t)BI*NN*NN];
__device__ unsigned char g_simM[(size_t)BI*NN*NN];

// monotonic float<->uint encoding for atomicMax
__device__ __forceinline__ unsigned fenc(float f) {
    unsigned u = __float_as_uint(f);
    return (u & 0x80000000u) ? ~u : (u | 0x80000000u);
}
__device__ __forceinline__ float fdec(unsigned u) {
    u = (u & 0x80000000u) ? (u & 0x7fffffffu) : ~u;
    return __uint_as_float(u);
}
__device__ __forceinline__ float lrelu(float x) { return x > 0.f ? x : 0.2f * x; }

__device__ __forceinline__ unsigned to_tf32(float f) {
    unsigned h; asm("cvt.rna.tf32.f32 %0, %1;" : "=r"(h) : "f"(f));
    return h;
}

#define MMA_TF32(c, a, b)                                                   \
    asm("mma.sync.aligned.m16n8k8.row.col.f32.tf32.tf32.f32 "               \
        "{%0,%1,%2,%3}, {%4,%5,%6,%7}, {%8,%9}, {%0,%1,%2,%3};"             \
        : "+f"((c)[0]), "+f"((c)[1]), "+f"((c)[2]), "+f"((c)[3])            \
        : "r"((a)[0]), "r"((a)[1]), "r"((a)[2]), "r"((a)[3]),               \
          "r"((b)[0]), "r"((b)[1]))

// ---------------- kernels ----------------
__global__ void init_kernel() {
    int t = threadIdx.x;
    if (t < BI*NH) g_M1[t] = 0u;
    if (t < BI)    g_M2[t] = 0u;
}

__global__ void pack_kernel(const float* __restrict__ simW, const float* __restrict__ gat1W,
                            const float* __restrict__ refW, const float* __restrict__ bboxW) {
    int idx = blockIdx.x * blockDim.x + threadIdx.x;
    if (idx >= DIN*WALLP) return;
    int k = idx / WALLP, j = idx % WALLP;
    float v = 0.f;
    if (j < COL_H1)        v = simW[k*SD + j];
    else if (j < COL_REF)  v = gat1W[k*64 + (j - COL_H1)];
    else if (j < COL_BBOX) { int jj = j - COL_REF;  int t = jj/NC; int c = jj%NC;
                             v = refW[(size_t)t*DIN*NC + (size_t)k*NC + c]; }
    else if (j < WALLN)    { int jj = j - COL_BBOX; int t = jj/80; int c = jj%80;
                             v = bboxW[(size_t)t*DIN*80 + (size_t)k*80 + c]; }
    g_Wall[idx] = v;
}

// C[4096,896] = A[4096,2048] @ g_Wall[2048,896] via tf32 mma.sync.
// BM=128 BN=64 BK=32; 8 warps as 4(m)x2(n), each warp 32x32.
// THREE=true adds residual passes (3xtf32) for near-fp32 precision.
template<bool THREE>
__global__ __launch_bounds__(256) void sgemm_tc(const float* __restrict__ A, int nblk0) {
    __shared__ float As[32*ASTR];
    __shared__ float Bs[32*BSTR];
    const int t = threadIdx.x;
    const int lane = t & 31, w = t >> 5;
    const int wm = w >> 1, wn = w & 1;
    const int m0 = blockIdx.y * 128;
    const int n0 = (blockIdx.x + nblk0) * 64;
    const int ar = t >> 3;            // 0..31
    const int ac0 = (t & 7) << 2;     // 0,4,...,28

    float acc[2][4][4];
#pragma unroll
    for (int mt = 0; mt < 2; mt++)
#pragma unroll
        for (int nt = 0; nt < 4; nt++)
#pragma unroll
            for (int i = 0; i < 4; i++) acc[mt][nt][i] = 0.f;

    for (int k0 = 0; k0 < DIN; k0 += 32) {
        __syncthreads();
        // stage A tile [k=32][m=128] (transposed, swizzled)
#pragma unroll
        for (int b = 0; b < 4; b++) {
            int r = ar + (b << 5);
            float4 v = *(const float4*)(A + (size_t)(m0 + r) * DIN + k0 + ac0);
#pragma unroll
            for (int j = 0; j < 4; j++) {
                int c = ac0 + j;
                As[c*ASTR + (r ^ (((c>>2)&7)<<2))] = ((const float*)&v)[j];
            }
        }
        // stage B tile [k=32][n=64] (row-major source, swizzled, vectorized)
        {
            int k = ar;
            int sb = ((k>>2)&7) << 2;
#pragma unroll
            for (int b = 0; b < 2; b++) {
                int nc = ac0 + (b << 5);
                float4 v = *(const float4*)(g_Wall + (size_t)(k0 + k) * WALLP + n0 + nc);
                *(float4*)&Bs[k*BSTR + (nc ^ sb)] = v;
            }
        }
        __syncthreads();
#pragma unroll
        for (int ks = 0; ks < 4; ks++) {
            unsigned ah[2][4], al[2][4], bh[4][2], bl[4][2];
#pragma unroll
            for (int mt = 0; mt < 2; mt++)
#pragma unroll
                for (int i = 0; i < 4; i++) {
                    int c = ks*8 + (lane & 3) + ((i >> 1) << 2);
                    int m = wm*32 + mt*16 + (lane >> 2) + ((i & 1) << 3);
                    float f = As[c*ASTR + (m ^ (((c>>2)&7)<<2))];
                    ah[mt][i] = to_tf32(f);
                    if (THREE) al[mt][i] = to_tf32(f - __uint_as_float(ah[mt][i]));
                }
#pragma unroll
            for (int nt = 0; nt < 4; nt++)
#pragma unroll
                for (int i = 0; i < 2; i++) {
                    int k = ks*8 + (lane & 3) + (i << 2);
                    int n = wn*32 + nt*8 + (lane >> 2);
                    float f = Bs[k*BSTR + (n ^ (((k>>2)&7)<<2))];
                    bh[nt][i] = to_tf32(f);
                    if (THREE) bl[nt][i] = to_tf32(f - __uint_as_float(bh[nt][i]));
                }
#pragma unroll
            for (int mt = 0; mt < 2; mt++)
#pragma unroll
                for (int nt = 0; nt < 4; nt++) {
                    MMA_TF32(acc[mt][nt], ah[mt], bh[nt]);
                    if (THREE) {
                        MMA_TF32(acc[mt][nt], al[mt], bh[nt]);
                        MMA_TF32(acc[mt][nt], ah[mt], bl[nt]);
                    }
                }
        }
    }
#pragma unroll
    for (int mt = 0; mt < 2; mt++)
#pragma unroll
        for (int nt = 0; nt < 4; nt++) {
            int row = m0 + wm*32 + mt*16 + (lane >> 2);
            int col = n0 + wn*32 + nt*8 + ((lane & 3) << 1);
            *(float2*)&g_Call[(size_t)row * WALLP + col] =
                make_float2(acc[mt][nt][0], acc[mt][nt][1]);
            *(float2*)&g_Call[(size_t)(row + 8) * WALLP + col] =
                make_float2(acc[mt][nt][2], acc[mt][nt][3]);
        }
}

// per-row L2 normalize of sim features (adds sim_b)
__global__ void normalize_kernel(const float* __restrict__ simb) {
    int r = blockIdx.x, tid = threadIdx.x;  // 128 threads
    const float* row = g_Call + (size_t)r * WALLP;
    float ss = 0.f;
    for (int c = tid; c < SD; c += 128) { float v = row[c] + simb[c]; ss += v * v; }
#pragma unroll
    for (int off = 16; off > 0; off >>= 1) ss += __shfl_xor_sync(0xffffffffu, ss, off);
    __shared__ float red[4];
    if ((tid & 31) == 0) red[tid >> 5] = ss;
    __syncthreads();
    float tot = red[0] + red[1] + red[2] + red[3];
    float inv = 1.f / (sqrtf(tot) + 1e-9f);
    for (int c = tid; c < SD; c += 128) {
        float v = row[c] + simb[c];
        g_SF[(size_t)r * SD + c] = v * inv;
    }
}

__global__ void edge1_kernel(const float* __restrict__ asrc, const float* __restrict__ adst) {
    int n = blockIdx.x * blockDim.x + threadIdx.x;
    if (n >= NODES) return;
    const float* h = g_Call + (size_t)n * WALLP + COL_H1;
    int img = n >> 10;
#pragma unroll
    for (int hh = 0; hh < NH; hh++) {
        float es = 0.f, ed = 0.f;
#pragma unroll
        for (int f = 0; f < NF; f++) {
            float v = h[hh * NF + f];
            es = fmaf(v, asrc[hh * NF + f], es);
            ed = fmaf(v, adst[hh * NF + f], ed);
        }
        g_ES1[n * NH + hh] = es;
        g_ED1[n * NH + hh] = ed;
        atomicMax(&g_M1[img * NH + hh], fenc(es));
    }
}

// IoU edge mask (byte per pair), 16 dsts per block
__global__ void iou_kernel(const float* __restrict__ boxes) {
    __shared__ float4 bx[NN];
    int img = blockIdx.y, tid = threadIdx.x;
    const float4* bsrc = (const float4*)(boxes + (size_t)img * NN * 4);
    for (int i = tid; i < NN; i += 256) bx[i] = bsrc[i];
    __syncthreads();
    unsigned char* M = g_iouM + (size_t)img * NN * NN;
    for (int idx = tid; idx < 16 * NN; idx += 256) {
        int dl = idx >> 10, s = idx & 1023;
        int d = blockIdx.x * 16 + dl;
        float4 A = bx[d], Bb = bx[s];
        float areaA = (A.z - A.x) * (A.w - A.y);
        float areaB = (Bb.z - Bb.x) * (Bb.w - Bb.y);
        float lx = fmaxf(A.x, Bb.x), ly = fmaxf(A.y, Bb.y);
        float rx = fminf(A.z, Bb.z), ry = fminf(A.w, Bb.w);
        float w = fmaxf(rx - lx, 0.f), hh = fmaxf(ry - ly, 0.f);
        float inter = w * hh;
        float iou = inter / (areaA + areaB - inter + 1e-9f);
        M[(size_t)d * NN + s] = (unsigned char)((iou >= 0.4f) || (s == d));
    }
}

// GAT1 aggregation: warp per dst, 8 dsts per block, smem-staged src chunks
__global__ __launch_bounds__(256) void gat1_agg_kernel(const float* __restrict__ b1) {
    int img = blockIdx.y;
    int warp = threadIdx.x >> 5, lane = threadIdx.x & 31;
    int d = blockIdx.x * 8 + warp;
    int gd = img * NN + d;
    __shared__ float sh_h1[128][65];
    __shared__ float sh_es[128][9];
    __shared__ unsigned char sh_m[8][128];
    float acc[64], den[NH], ed[NH], shift[NH];
#pragma unroll
    for (int i = 0; i < 64; i++) acc[i] = 0.f;
#pragma unroll
    for (int h = 0; h < NH; h++) {
        den[h] = 0.f;
        ed[h] = g_ED1[gd * NH + h];
        shift[h] = lrelu(fdec(g_M1[img * NH + h]) + ed[h]);
    }
    for (int c0 = 0; c0 < NN; c0 += 128) {
        __syncthreads();
        for (int i = threadIdx.x; i < 128 * 64; i += 256) {
            int r = i >> 6, c = i & 63;
            sh_h1[r][c] = g_Call[(size_t)(img * NN + c0 + r) * WALLP + COL_H1 + c];
        }
        for (int i = threadIdx.x; i < 128 * 8; i += 256) {
            int r = i >> 3, c = i & 7;
            sh_es[r][c] = g_ES1[(img * NN + c0 + r) * NH + c];
        }
        {
            const unsigned* mrow = (const unsigned*)(g_iouM + (size_t)img * NN * NN + (size_t)d * NN + c0);
            ((unsigned*)sh_m[warp])[lane] = mrow[lane];
        }
        __syncthreads();
        for (int p = 0; p < 4; p++) {
            int sl = p * 32 + lane;
            bool mb = sh_m[warp][sl] != 0;
            if (!__any_sync(0xffffffffu, mb)) continue;
            if (mb) {
#pragma unroll
                for (int h = 0; h < NH; h++) {
                    float w = __expf(lrelu(sh_es[sl][h] + ed[h]) - shift[h]);
                    den[h] += w;
#pragma unroll
                    for (int f = 0; f < NF; f++)
                        acc[h * 8 + f] = fmaf(w, sh_h1[sl][h * 8 + f], acc[h * 8 + f]);
                }
            }
        }
    }
#pragma unroll
    for (int off = 16; off > 0; off >>= 1) {
#pragma unroll
        for (int i = 0; i < 64; i++) acc[i] += __shfl_xor_sync(0xffffffffu, acc[i], off);
#pragma unroll
        for (int h = 0; h < NH; h++) den[h] += __shfl_xor_sync(0xffffffffu, den[h], off);
    }
    if (lane == 0) {
#pragma unroll
        for (int i = 0; i < 64; i++) {
            float v = acc[i] / den[i >> 3] + b1[i];
            g_N1[(size_t)gd * 64 + i] = v > 0.f ? v : expm1f(v);
        }
    }
}

__global__ void gat2_prep_kernel(const float* __restrict__ W2,
                                 const float* __restrict__ asrc2,
                                 const float* __restrict__ adst2) {
    int n = blockIdx.x * blockDim.x + threadIdx.x;
    if (n >= NODES) return;
    int img = n >> 10;
    float x[64];
#pragma unroll
    for (int k = 0; k < 64; k++) x[k] = g_N1[(size_t)n * 64 + k];
    float es = 0.f, ed = 0.f;
    for (int c = 0; c < NC; c++) {
        float a = 0.f;
#pragma unroll
        for (int k = 0; k < 64; k++) a = fmaf(x[k], W2[k * NC + c], a);
        g_H2[n * NC + c] = a;
        es = fmaf(a, asrc2[c], es);
        ed = fmaf(a, adst2[c], ed);
    }
    g_ES2[n] = es;
    g_ED2[n] = ed;
    atomicMax(&g_M2[img], fenc(es));
}

// per-image gram of normalized sim features -> byte mask, tf32 tensor cores.
// BM=128(s) BN=64(d) BK=32, same structure as sgemm_tc (single pass).
__global__ __launch_bounds__(256) void gram_tc() {
    __shared__ float As[32*ASTR];
    __shared__ float Bs[32*BSTR];
    const int img = blockIdx.z;
    const float* A = g_SF + (size_t)img * NN * SD;
    const int t = threadIdx.x;
    const int lane = t & 31, w = t >> 5;
    const int wm = w >> 1, wn = w & 1;
    const int m0 = blockIdx.y * 128;   // source (s) rows
    const int n0 = blockIdx.x * 64;    // destination (d) rows
    const int ar = t >> 3;
    const int ac0 = (t & 7) << 2;

    float acc[2][4][4];
#pragma unroll
    for (int mt = 0; mt < 2; mt++)
#pragma unroll
        for (int nt = 0; nt < 4; nt++)
#pragma unroll
            for (int i = 0; i < 4; i++) acc[mt][nt][i] = 0.f;

    for (int k0 = 0; k0 < SD; k0 += 32) {
        __syncthreads();
#pragma unroll
        for (int b = 0; b < 4; b++) {
            int r = ar + (b << 5);
            float4 v = *(const float4*)(A + (size_t)(m0 + r) * SD + k0 + ac0);
#pragma unroll
            for (int j = 0; j < 4; j++) {
                int c = ac0 + j;
                As[c*ASTR + (r ^ (((c>>2)&7)<<2))] = ((const float*)&v)[j];
            }
        }
        // B side: rows n0..n0+63 of SF, transposed into [k][n]
#pragma unroll
        for (int b = 0; b < 2; b++) {
            int n = ar + (b << 5);
            float4 v = *(const float4*)(A + (size_t)(n0 + n) * SD + k0 + ac0);
#pragma unroll
            for (int j = 0; j < 4; j++) {
                int c = ac0 + j;
                Bs[c*BSTR + (n ^ (((c>>2)&7)<<2))] = ((const float*)&v)[j];
            }
        }
        __syncthreads();
#pragma unroll
        for (int ks = 0; ks < 4; ks++) {
            unsigned ah[2][4], bh[4][2];
#pragma unroll
            for (int mt = 0; mt < 2; mt++)
#pragma unroll
                for (int i = 0; i < 4; i++) {
                    int c = ks*8 + (lane & 3) + ((i >> 1) << 2);
                    int m = wm*32 + mt*16 + (lane >> 2) + ((i & 1) << 3);
                    ah[mt][i] = to_tf32(As[c*ASTR + (m ^ (((c>>2)&7)<<2))]);
                }
#pragma unroll
            for (int nt = 0; nt < 4; nt++)
#pragma unroll
                for (int i = 0; i < 2; i++) {
                    int k = ks*8 + (lane & 3) + (i << 2);
                    int n = wn*32 + nt*8 + (lane >> 2);
                    bh[nt][i] = to_tf32(Bs[k*BSTR + (n ^ (((k>>2)&7)<<2))]);
                }
#pragma unroll
            for (int mt = 0; mt < 2; mt++)
#pragma unroll
                for (int nt = 0; nt < 4; nt++)
                    MMA_TF32(acc[mt][nt], ah[mt], bh[nt]);
        }
    }
    unsigned char* M = g_simM + (size_t)img * NN * NN;
#pragma unroll
    for (int mt = 0; mt < 2; mt++)
#pragma unroll
        for (int nt = 0; nt < 4; nt++) {
            int s0 = m0 + wm*32 + mt*16 + (lane >> 2);
            int d0 = n0 + wn*32 + nt*8 + ((lane & 3) << 1);
            M[(size_t)d0 * NN + s0]       = (unsigned char)((acc[mt][nt][0] >= 0.4f) || (s0 == d0));
            M[(size_t)(d0+1) * NN + s0]   = (unsigned char)((acc[mt][nt][1] >= 0.4f) || (s0 == d0+1));
            M[(size_t)d0 * NN + s0+8]     = (unsigned char)((acc[mt][nt][2] >= 0.4f) || (s0+8 == d0));
            M[(size_t)(d0+1) * NN + s0+8] = (unsigned char)((acc[mt][nt][3] >= 0.4f) || (s0+8 == d0+1));
        }
}

__global__ __launch_bounds__(256) void gat2_agg_kernel(const float* __restrict__ b2) {
    int img = blockIdx.y;
    int warp = threadIdx.x >> 5, lane = threadIdx.x & 31;
    int d = blockIdx.x * 8 + warp;
    int gd = img * NN + d;
    __shared__ float sh_h2[128][21];
    __shared__ float sh_es[128];
    __shared__ unsigned char sh_m[8][128];
    float acc[NC], den = 0.f;
#pragma unroll
    for (int c = 0; c < NC; c++) acc[c] = 0.f;
    float ed = g_ED2[gd];
    float shift = lrelu(fdec(g_M2[img]) + ed);
    for (int c0 = 0; c0 < NN; c0 += 128) {
        __syncthreads();
        for (int i = threadIdx.x; i < 128 * NC; i += 256) {
            int r = i / NC, c = i % NC;
            sh_h2[r][c] = g_H2[(img * NN + c0 + r) * NC + c];
        }
        if (threadIdx.x < 128) sh_es[threadIdx.x] = g_ES2[img * NN + c0 + threadIdx.x];
        {
            const unsigned* mrow = (const unsigned*)(g_simM + (size_t)img * NN * NN + (size_t)d * NN + c0);
            ((unsigned*)sh_m[warp])[lane] = mrow[lane];
        }
        __syncthreads();
        for (int p = 0; p < 4; p++) {
            int sl = p * 32 + lane;
            bool mb = sh_m[warp][sl] != 0;
            if (!__any_sync(0xffffffffu, mb)) continue;
            if (mb) {
                float w = __expf(lrelu(sh_es[sl] + ed) - shift);
                den += w;
#pragma unroll
                for (int c = 0; c < NC; c++) acc[c] = fmaf(w, sh_h2[sl][c], acc[c]);
            }
        }
    }
#pragma unroll
    for (int off = 16; off > 0; off >>= 1) {
#pragma unroll
        for (int c = 0; c < NC; c++) acc[c] += __shfl_xor_sync(0xffffffffu, acc[c], off);
        den += __shfl_xor_sync(0xffffffffu, den, off);
    }
    if (lane == 0) {
#pragma unroll
        for (int c = 0; c < NC; c++) g_N2[(size_t)gd * NC + c] = acc[c] / den + b2[c];
    }
}

__global__ void node_kernel(const float* __restrict__ nW, const float* __restrict__ nb,
                            float* __restrict__ out) {
    int n = blockIdx.x * blockDim.x + threadIdx.x;
    if (n >= NODES) return;
    float x[NC], v[NC];
#pragma unroll
    for (int c = 0; c < NC; c++) x[c] = g_N2[(size_t)n * NC + c];
#pragma unroll
    for (int c = 0; c < NC; c++) {
        float a = nb[c];
#pragma unroll
        for (int cc = 0; cc < NC; cc++) a = fmaf(x[cc], nW[cc * NC + c], a);
        v[c] = a;
    }
    float m = v[0];
#pragma unroll
    for (int c = 1; c < NC; c++) m = fmaxf(m, v[c]);
    float s = 0.f;
#pragma unroll
    for (int c = 0; c < NC; c++) { v[c] = __expf(v[c] - m); s += v[c]; }
    float inv = 1.f / s;
#pragma unroll
    for (int c = 0; c < NC; c++) out[OUT_NODE + (size_t)n * NC + c] = v[c] * inv;
}

__global__ void graph_kernel(float* __restrict__ out) {
    int img = blockIdx.x, c = blockIdx.y, tid = threadIdx.x;  // 256 threads
    float s = 0.f;
    for (int node = tid; node < NN; node += 256)
        s += out[OUT_NODE + (size_t)(img * NN + node) * NC + c];
#pragma unroll
    for (int off = 16; off > 0; off >>= 1) s += __shfl_xor_sync(0xffffffffu, s, off);
    __shared__ float red[8];
    if ((tid & 31) == 0) red[tid >> 5] = s;
    __syncthreads();
    if (tid == 0) {
        float tot = 0.f;
#pragma unroll
        for (int i = 0; i < 8; i++) tot += red[i];
        out[img * NC + c] = tot * (1.f / (float)NN);
    }
}

__global__ void scatter_kernel(const float* __restrict__ refb, const float* __restrict__ bboxb,
                               float* __restrict__ out) {
    int idx = blockIdx.x * blockDim.x + threadIdx.x;
    const int REF_TOT = 3 * NODES * NC;       // 245760
    const int BBOX_TOT = 3 * NODES * 80;      // 983040
    if (idx < REF_TOT) {
        int k = idx / (NODES * NC), r = idx % (NODES * NC);
        int n = r / NC, c = r % NC;
        out[OUT_REF + idx] = g_Call[(size_t)n * WALLP + COL_REF + k * NC + c] + refb[k * NC + c];
    } else {
        int j = idx - REF_TOT;
        if (j >= BBOX_TOT) return;
        int k = j / (NODES * 80), r = j % (NODES * 80);
        int n = r / 80, c = r % 80;
        out[OUT_BBOX + j] = g_Call[(size_t)n * WALLP + COL_BBOX + k * 80 + c] + bboxb[k * 80 + c];
    }
}

// ---------------- launch ----------------
extern "C" void kernel_launch(void* const* d_in, const int* in_sizes, int n_in,
                              void* d_out, int out_size) {
    const float* x1     = (const float*)d_in[0];
    const float* boxes  = (const float*)d_in[1];
    const float* simW   = (const float*)d_in[2];
    const float* simb   = (const float*)d_in[3];
    const float* gat1W  = (const float*)d_in[4];
    const float* asrc1  = (const float*)d_in[5];
    const float* adst1  = (const float*)d_in[6];
    const float* b1     = (const float*)d_in[7];
    const float* gat2W  = (const float*)d_in[8];
    const float* asrc2  = (const float*)d_in[9];
    const float* adst2  = (const float*)d_in[10];
    const float* b2     = (const float*)d_in[11];
    const float* nodeW  = (const float*)d_in[12];
    const float* nodeb  = (const float*)d_in[13];
    const float* refW   = (const float*)d_in[14];
    const float* refb   = (const float*)d_in[15];
    const float* bboxW  = (const float*)d_in[16];
    const float* bboxb  = (const float*)d_in[17];
    float* out = (float*)d_out;

    init_kernel<<<1, 64>>>();
    pack_kernel<<<(DIN * WALLP + 255) / 256, 256>>>(simW, gat1W, refW, bboxW);
    // cols 0..511 (sim features, mask-only consumer): single-pass tf32
    sgemm_tc<false><<<dim3(8, 32), 256>>>(x1, 0);
    // cols 512..895 (gat1 + ref/bbox, output-critical): 3x tf32 split
    sgemm_tc<true><<<dim3(6, 32), 256>>>(x1, 8);
    normalize_kernel<<<NODES, 128>>>(simb);
    edge1_kernel<<<NODES / 256, 256>>>(asrc1, adst1);
    iou_kernel<<<dim3(NN / 16, BI), 256>>>(boxes);
    gat1_agg_kernel<<<dim3(NN / 8, BI), 256>>>(b1);
    gat2_prep_kernel<<<NODES / 256, 256>>>(gat2W, asrc2, adst2);
    gram_tc<<<dim3(NN / 64, NN / 128, BI), 256>>>();
    gat2_agg_kernel<<<dim3(NN / 8, BI), 256>>>(b2);
    node_kernel<<<NODES / 256, 256>>>(nodeW, nodeb, out);
    graph_kernel<<<dim3(BI, NC), 256>>>(out);
    scatter_kernel<<<(3 * NODES * NC + 3 * NODES * 80 + 255) / 256, 256>>>(refb, bboxb, out);
}